// round 2
// baseline (speedup 1.0000x reference)
#include <cuda_runtime.h>
#include <math.h>

#define ORDER 2048
#define INDIM 64
#define TLEN  4096
#define CHK   16
#define NC    256   // TLEN / CHK

typedef unsigned long long ull;

// ---------------- static device scratch (allocation-free) ----------------
__device__ float g_BU[CHK * ORDER * NC];    // 32 MB, chunk-major: BU[j][r][c]
__device__ float g_P0[ORDER * ORDER];       // 16 MB
__device__ float g_P1[ORDER * ORDER];       // 16 MB
__device__ float g_H0[ORDER * NC];          // 2 MB
__device__ float g_H1[ORDER * NC];          // 2 MB
__device__ float g_part[4 * ORDER * NC];    // 8 MB split-K partials
__device__ float g_bv[2 * ORDER];           // boundary vector ping-pong
__device__ unsigned int g_bar_count;
__device__ volatile unsigned int g_bar_gen;

// ---------------- packed f32x2 helpers ----------------
__device__ __forceinline__ ull fma2(ull a, ull b, ull c) {
    ull d;
    asm("fma.rn.f32x2 %0, %1, %2, %3;" : "=l"(d) : "l"(a), "l"(b), "l"(c));
    return d;
}
__device__ __forceinline__ ull dup2(float x) {
    ull d;
    asm("mov.b64 %0, {%1, %1};" : "=l"(d) : "f"(x));
    return d;
}
__device__ __forceinline__ float2 unpk(ull v) {
    float2 f;
    asm("mov.b64 {%0, %1}, %2;" : "=f"(f.x), "=f"(f.y) : "l"(v));
    return f;
}

// ---------------- single-wave spin grid barrier ----------------
__device__ __forceinline__ void grid_barrier(unsigned int nb) {
    __syncthreads();
    if (threadIdx.x == 0) {
        __threadfence();
        unsigned int gen = g_bar_gen;
        if (atomicAdd(&g_bar_count, 1u) == nb - 1u) {
            g_bar_count = 0u;
            __threadfence();
            g_bar_gen = gen + 1u;
        } else {
            while (g_bar_gen == gen) { __nanosleep(32); }
        }
        __threadfence();
    }
    __syncthreads();
}

// ---------------- BU precompute: BU[j][r][c] = sum_d B[r][d] * u[d][c*16+j] ----
__global__ void bu_kernel(const float* __restrict__ B, const float* __restrict__ u,
                          float* __restrict__ BU) {
    int t = blockIdx.x * 32 + threadIdx.x;   // blockDim (32,8)
    int r = blockIdx.y * 8 + threadIdx.y;
    float s = 0.f;
#pragma unroll
    for (int d = 0; d < INDIM; d++)
        s += B[r * INDIM + d] * u[d * TLEN + t];
    BU[((size_t)(t & 15) * ORDER + r) * NC + (t >> 4)] = s;
}

// ---------------- SGEMM: C(+zoff) = A[2048 x K] @ B[K x N] ----------------
// BM=BN=128, BK=16, 256 threads, 8x8 per thread, f32x2 accumulators.
// blockIdx.z = split-K slice (length KS). lda hardcoded 2048.
__global__ void __launch_bounds__(256) gemm128(
    const float* __restrict__ A, const float* __restrict__ B,
    float* __restrict__ C, int N, int KS)
{
    __shared__ float As[16][132];   // transposed A tile, padded
    __shared__ float Bs[16][128];

    int tid = threadIdx.x;
    int bm = blockIdx.y * 128, bn = blockIdx.x * 128;
    int kbase = blockIdx.z * KS;

    const float* Ap = A + (size_t)bm * ORDER + kbase;
    const float* Bp = B + (size_t)kbase * N + bn;

    int arow = tid >> 2, acol = (tid & 3) * 4;   // rows arow, arow+64
    int brow = tid >> 5, bcol = (tid & 31) * 4;  // rows brow, brow+8
    int tn = (tid & 15) * 8, tm = (tid >> 4) * 8;

    ull acc[8][4];
#pragma unroll
    for (int i = 0; i < 8; i++)
#pragma unroll
        for (int j = 0; j < 4; j++) acc[i][j] = 0ull;

    float4 pa0 = *(const float4*)&Ap[(size_t)arow * ORDER + acol];
    float4 pa1 = *(const float4*)&Ap[(size_t)(arow + 64) * ORDER + acol];
    float4 pb0 = *(const float4*)&Bp[(size_t)brow * N + bcol];
    float4 pb1 = *(const float4*)&Bp[(size_t)(brow + 8) * N + bcol];

    int ntiles = KS / 16;
    for (int t = 0; t < ntiles; t++) {
        // store current tile (A transposed)
        As[acol + 0][arow] = pa0.x; As[acol + 1][arow] = pa0.y;
        As[acol + 2][arow] = pa0.z; As[acol + 3][arow] = pa0.w;
        As[acol + 0][arow + 64] = pa1.x; As[acol + 1][arow + 64] = pa1.y;
        As[acol + 2][arow + 64] = pa1.z; As[acol + 3][arow + 64] = pa1.w;
        *(float4*)&Bs[brow][bcol] = pb0;
        *(float4*)&Bs[brow + 8][bcol] = pb1;
        __syncthreads();

        if (t + 1 < ntiles) {  // prefetch next tile (overlaps compute)
            Ap += 16; Bp += (size_t)16 * N;
            pa0 = *(const float4*)&Ap[(size_t)arow * ORDER + acol];
            pa1 = *(const float4*)&Ap[(size_t)(arow + 64) * ORDER + acol];
            pb0 = *(const float4*)&Bp[(size_t)brow * N + bcol];
            pb1 = *(const float4*)&Bp[(size_t)(brow + 8) * N + bcol];
        }

#pragma unroll
        for (int k = 0; k < 16; k++) {
            float4 a0 = *(const float4*)&As[k][tm];
            float4 a1 = *(const float4*)&As[k][tm + 4];
            ulonglong2 q0 = *(const ulonglong2*)&Bs[k][tn];
            ulonglong2 q1 = *(const ulonglong2*)&Bs[k][tn + 4];
            float av[8] = {a0.x, a0.y, a0.z, a0.w, a1.x, a1.y, a1.z, a1.w};
#pragma unroll
            for (int i = 0; i < 8; i++) {
                ull ad = dup2(av[i]);
                acc[i][0] = fma2(ad, q0.x, acc[i][0]);
                acc[i][1] = fma2(ad, q0.y, acc[i][1]);
                acc[i][2] = fma2(ad, q1.x, acc[i][2]);
                acc[i][3] = fma2(ad, q1.y, acc[i][3]);
            }
        }
        __syncthreads();
    }

    float* Cp = C + (size_t)blockIdx.z * ORDER * N + (size_t)(bm + tm) * N + bn + tn;
#pragma unroll
    for (int i = 0; i < 8; i++) {
        float2 v0 = unpk(acc[i][0]), v1 = unpk(acc[i][1]);
        float2 v2 = unpk(acc[i][2]), v3 = unpk(acc[i][3]);
        *(float4*)&Cp[(size_t)i * N]     = make_float4(v0.x, v0.y, v1.x, v1.y);
        *(float4*)&Cp[(size_t)i * N + 4] = make_float4(v2.x, v2.y, v3.x, v3.y);
    }
}

// ---------------- split-K reduce + BU add (+ optional tanh emit) ----------
__global__ void reduce_kernel(const float* __restrict__ part,
                              const float* __restrict__ bu,
                              float* __restrict__ Hout,
                              float* __restrict__ outp, int j) {
    const int SZ = ORDER * NC;
    int idx = blockIdx.x * 256 + threadIdx.x;
    float v = part[idx] + part[idx + SZ] + part[idx + 2 * SZ] + part[idx + 3 * SZ]
            + bu[idx];
    Hout[idx] = v;
    if (outp) {
        int r = idx >> 8, c = idx & 255;
        outp[(size_t)r * TLEN + c * CHK + j] = tanhf(v);
    }
}

// ---------------- boundary seed emit: out[:, c*16] = tanh(b_c) --------------
__global__ void seed_emit(const float* __restrict__ Bm, float* __restrict__ outp) {
    int idx = blockIdx.x * 256 + threadIdx.x;
    int r = idx >> 8, c = idx & 255;
    outp[(size_t)r * TLEN + c * CHK] = tanhf(Bm[idx]);
}

// ---------------- persistent boundary scan: b_{c+1} = A16 b_c + D_c --------
// 128 CTAs x 256 threads; each thread holds 128 floats of A16 (as 32 ull2).
__global__ void __launch_bounds__(256, 1) scan_kernel(
    const float* __restrict__ A16, const float* __restrict__ D,
    float* __restrict__ Bm)
{
    __shared__ float bs[ORDER];
    __shared__ float red[16][9];

    int tid = threadIdx.x;
    int cta = blockIdx.x;                 // 128 CTAs, 16 rows each
    int rloc = tid & 15;
    int row = cta * 16 + rloc;
    int seg = (tid >> 4) * 128;

    // A16 row segment into registers, packed as f32x2 pairs
    ulonglong2 a2[32];
    const ulonglong2* Arow = (const ulonglong2*)(A16 + (size_t)row * ORDER + seg);
#pragma unroll
    for (int i = 0; i < 32; i++) a2[i] = Arow[i];

    // b_0 = ones (benign multi-CTA same-value writes)
    for (int i = tid; i < ORDER; i += 256) g_bv[i] = 1.0f;
    if (tid < 16) Bm[(size_t)(cta * 16 + tid) * NC + 0] = 1.0f;
    grid_barrier(128);

    for (int c = 0; c < NC - 1; c++) {
        const float4* bsrc = (const float4*)(g_bv + (c & 1) * ORDER);
        float4* bdst4 = (float4*)bs;
        bdst4[tid] = bsrc[tid];
        bdst4[tid + 256] = bsrc[tid + 256];
        __syncthreads();

        ull pA = 0ull, pB = 0ull;
        const ulonglong2* b2 = (const ulonglong2*)(bs + seg);
#pragma unroll
        for (int i = 0; i < 32; i++) {
            pA = fma2(a2[i].x, b2[i].x, pA);
            pB = fma2(a2[i].y, b2[i].y, pB);
        }
        float2 fa = unpk(pA), fb = unpk(pB);
        float p = (fa.x + fa.y) + (fb.x + fb.y);
        p += __shfl_down_sync(0xffffffffu, p, 16);
        if ((tid & 31) < 16) red[rloc][tid >> 5] = p;
        __syncthreads();

        if (tid < 16) {
            int rr = cta * 16 + tid;
            float s = red[tid][0] + red[tid][1] + red[tid][2] + red[tid][3]
                    + red[tid][4] + red[tid][5] + red[tid][6] + red[tid][7]
                    + D[(size_t)rr * NC + c];
            g_bv[((c + 1) & 1) * ORDER + rr] = s;
            Bm[(size_t)rr * NC + c + 1] = s;
        }
        grid_barrier(128);
    }
}

// ---------------- host orchestration ----------------
extern "C" void kernel_launch(void* const* d_in, const int* in_sizes, int n_in,
                              void* d_out, int out_size) {
    // identify inputs by size (u: 64*4096, weight_a: 2048*2048, weight_b: 2048*64)
    const float* u = nullptr; const float* wa = nullptr; const float* wb = nullptr;
    for (int i = 0; i < n_in; i++) {
        if (in_sizes[i] == INDIM * TLEN)       u  = (const float*)d_in[i];
        else if (in_sizes[i] == ORDER * ORDER) wa = (const float*)d_in[i];
        else if (in_sizes[i] == ORDER * INDIM) wb = (const float*)d_in[i];
    }
    float* out = (float*)d_out;

    float *BU, *P0, *P1, *H0, *H1, *part;
    cudaGetSymbolAddress((void**)&BU, g_BU);
    cudaGetSymbolAddress((void**)&P0, g_P0);
    cudaGetSymbolAddress((void**)&P1, g_P1);
    cudaGetSymbolAddress((void**)&H0, g_H0);
    cudaGetSymbolAddress((void**)&H1, g_H1);
    cudaGetSymbolAddress((void**)&part, g_part);

    const int SZC = ORDER * NC;

    // 1) BU = B @ u, chunk-major
    bu_kernel<<<dim3(TLEN / 32, ORDER / 8), dim3(32, 8)>>>(wb, u, BU);

    // 2) A^16 via repeated squaring (full-K GEMMs, grid 16x16)
    gemm128<<<dim3(16, 16, 1), 256>>>(wa, wa, P0, ORDER, ORDER);  // A^2
    gemm128<<<dim3(16, 16, 1), 256>>>(P0, P0, P1, ORDER, ORDER);  // A^4
    gemm128<<<dim3(16, 16, 1), 256>>>(P1, P1, P0, ORDER, ORDER);  // A^8
    gemm128<<<dim3(16, 16, 1), 256>>>(P0, P0, P1, ORDER, ORDER);  // A^16

    // 3) Pass 1: chunk-local contributions. H_1 = BU[0]; H_{g+1} = A H_g + BU[g]
    const float* Hin = BU;
    float* Hout = H0;
    for (int g = 1; g <= 15; g++) {
        gemm128<<<dim3(2, 16, 4), 256>>>(wa, Hin, part, NC, ORDER / 4);
        reduce_kernel<<<SZC / 256, 256>>>(part, BU + (size_t)g * SZC, Hout,
                                          nullptr, 0);
        Hin = Hout;
        Hout = (Hout == H0) ? H1 : H0;
    }
    // D = g_H0 (g=15 output)

    // 4) serial boundary scan: boundaries -> g_H1
    scan_kernel<<<128, 256>>>(P1, H0, H1);

    // 5) Pass 3: seed = boundaries, emit tanh for every timestep
    seed_emit<<<SZC / 256, 256>>>(H1, out);
    Hin = H1; Hout = H0;
    for (int j = 1; j <= 15; j++) {
        gemm128<<<dim3(2, 16, 4), 256>>>(wa, Hin, part, NC, ORDER / 4);
        reduce_kernel<<<SZC / 256, 256>>>(part, BU + (size_t)(j - 1) * SZC, Hout,
                                          out, j);
        Hin = Hout;
        Hout = (Hout == H0) ? H1 : H0;
    }
}